// round 16
// baseline (speedup 1.0000x reference)
#include <cuda_runtime.h>
#include <cuda_bf16.h>
#include <cstdint>
#include <float.h>

// AttentionSelector (R15 = R14 with 8B cp.async: repre rows are only
// 8B-aligned (2760B row pitch), so 16B cp.async traps on odd rows).
//  L = repre @ rel^T once (split-bf16 mma, err ~2^-16), then per-bag softmax
//  over gathered L[i,labels[i]] + weighted sum of L rows.
//   K0: rel -> 2-way bf16 split g_B1/g_B2 [64][704].
//   K1: L[200000][64]: A staged raw f32 via cp.async(8B) 2-stage pipeline,
//       split-bf16 conversion at fragment build; B fragments from gmem
//       (90 KB, L1/L2-resident). 3-term mma: A1B1 + A1B2 + A2B1.
//   K2: per-bag softmax + weighted sum of L rows -> out.
// scope/labels are int32 on device (JAX x64-disabled downgrades int64).

static constexpr int Dd   = 690;
static constexpr int Kpad = 704;
static constexpr int RR   = 53;
static constexpr int Npad = 64;
static constexpr int Mmax = 200000;
static constexpr int KC   = 32;          // k per stage
static constexpr int KI   = Kpad / KC;   // 22
static constexpr int SAF  = 36;          // A f32 smem row stride (144B)

__device__ float          g_L[(size_t)Mmax * Npad];   // 51.2 MB
__device__ __nv_bfloat16  g_B1[Npad * Kpad];
__device__ __nv_bfloat16  g_B2[Npad * Kpad];

__device__ __forceinline__ float wmax(float v) {
#pragma unroll
    for (int o = 16; o; o >>= 1) v = fmaxf(v, __shfl_xor_sync(0xffffffffu, v, o));
    return v;
}

#define MMA_BF16(c, a, b0_, b1_)                                              \
    asm volatile(                                                             \
        "mma.sync.aligned.m16n8k16.row.col.f32.bf16.bf16.f32 "                \
        "{%0,%1,%2,%3}, {%4,%5,%6,%7}, {%8,%9}, {%0,%1,%2,%3};"               \
        : "+f"((c)[0]), "+f"((c)[1]), "+f"((c)[2]), "+f"((c)[3])              \
        : "r"((a)[0]), "r"((a)[1]), "r"((a)[2]), "r"((a)[3]),                 \
          "r"(b0_), "r"(b1_))

#define CP_ASYNC_8(dst, src)                                                  \
    asm volatile("cp.async.ca.shared.global [%0], [%1], 8;" ::                \
                 "r"(dst), "l"(src))
#define CP_ASYNC_COMMIT() asm volatile("cp.async.commit_group;")
#define CP_ASYNC_WAIT(n)  asm volatile("cp.async.wait_group %0;" :: "n"(n))

__device__ __forceinline__ void cvt_split(const float* p, uint32_t& f1, uint32_t& f2) {
    const float2 v = *reinterpret_cast<const float2*>(p);
    __nv_bfloat162 h1, h2;
    h1.x = __float2bfloat16(v.x);
    h1.y = __float2bfloat16(v.y);
    h2.x = __float2bfloat16(v.x - __bfloat162float(h1.x));
    h2.y = __float2bfloat16(v.y - __bfloat162float(h1.y));
    f1 = *reinterpret_cast<uint32_t*>(&h1);
    f2 = *reinterpret_cast<uint32_t*>(&h2);
}

// ---------------- K0: rel -> split-bf16, [n][k] padded -------------------
__global__ void convert_kernel(const float* __restrict__ rel) {
    const int idx = blockIdx.x * blockDim.x + threadIdx.x;
    if (idx >= Npad * Kpad) return;
    const int n = idx / Kpad;
    const int k = idx - n * Kpad;
    float v = (n < RR && k < Dd) ? rel[n * Dd + k] : 0.f;
    const __nv_bfloat16 b1 = __float2bfloat16(v);
    const __nv_bfloat16 b2 = __float2bfloat16(v - __bfloat162float(b1));
    g_B1[idx] = b1;
    g_B2[idx] = b2;
}

// ---------------- K1: L = repre @ rel^T ----------------------------------
__global__ __launch_bounds__(256) void gemm_kernel(
    const float* __restrict__ repre, int Mrows)
{
    __shared__ float sAf[2][128][SAF];   // 36.9 KB

    const int tid  = threadIdx.x;
    const int lane = tid & 31;
    const int wid  = tid >> 5;
    const int gid  = lane >> 2;   // 0..7
    const int tg   = lane & 3;    // 0..3
    const int wm   = wid & 3;     // 4 m-tiles of 32
    const int wn   = wid >> 2;    // 2 n-tiles of 32
    const int m0   = blockIdx.x * 128;

    // A staging: 2 threads/row; thread covers 8 float2 chunks (64B)
    const int stA_m   = tid >> 1;            // 0..127
    const int pBase   = (tid & 1) * 8;       // float2 chunk base: 0 or 8
    const bool rowOK  = (m0 + stA_m) < Mrows;
    const float* arow = repre + (size_t)(m0 + stA_m) * Dd;

    uint32_t smem_base;
    asm("{ .reg .u64 t; cvta.to.shared.u64 t, %1; cvt.u32.u64 %0, t; }"
        : "=r"(smem_base) : "l"(&sAf[0][0][0]));

    float acc[2][4][4];
#pragma unroll
    for (int mi = 0; mi < 2; mi++)
#pragma unroll
        for (int ni = 0; ni < 4; ni++)
#pragma unroll
            for (int q = 0; q < 4; q++) acc[mi][ni][q] = 0.f;

    const uint32_t* gB1u = reinterpret_cast<const uint32_t*>(g_B1);
    const uint32_t* gB2u = reinterpret_cast<const uint32_t*>(g_B2);

    // ---- stage loader: 8 x 8B cp.async per thread (8B-aligned everywhere;
    //      Dd=690 is even so pairs are never split — exact tail) ----
    auto load_stage = [&](int kt, int stage) {
#pragma unroll
        for (int it = 0; it < 8; it++) {
            const int p  = pBase + it;             // float2 chunk in tile
            const int gk = kt * KC + p * 2;        // element index
            const uint32_t dst = smem_base +
                (uint32_t)(stage * 128 * SAF + stA_m * SAF + p * 2) * 4u;
            if (rowOK && gk + 2 <= Dd) {
                CP_ASYNC_8(dst, arow + gk);
            } else {
                *reinterpret_cast<float2*>(&sAf[stage][stA_m][p * 2]) =
                    make_float2(0.f, 0.f);
            }
        }
    };

    load_stage(0, 0);
    CP_ASYNC_COMMIT();

    for (int kt = 0; kt < KI; kt++) {
        const int cur = kt & 1;
        if (kt + 1 < KI) {
            load_stage(kt + 1, cur ^ 1);
            CP_ASYNC_COMMIT();
            CP_ASYNC_WAIT(1);
        } else {
            CP_ASYNC_WAIT(0);
        }
        __syncthreads();

        const int k0 = kt * KC;
#pragma unroll
        for (int s = 0; s < KC; s += 16) {
            // build A fragments (both splits from one f32 float2 load)
            uint32_t A1f[2][4], A2f[2][4];
#pragma unroll
            for (int mi = 0; mi < 2; mi++) {
                const int mb = wm * 32 + mi * 16;
                cvt_split(&sAf[cur][mb + gid    ][s + tg * 2],     A1f[mi][0], A2f[mi][0]);
                cvt_split(&sAf[cur][mb + gid + 8][s + tg * 2],     A1f[mi][1], A2f[mi][1]);
                cvt_split(&sAf[cur][mb + gid    ][s + tg * 2 + 8], A1f[mi][2], A2f[mi][2]);
                cvt_split(&sAf[cur][mb + gid + 8][s + tg * 2 + 8], A1f[mi][3], A2f[mi][3]);
            }
#pragma unroll
            for (int ni = 0; ni < 4; ni++) {
                const int nb = wn * 32 + ni * 8 + gid;
                const int bi = nb * (Kpad / 2) + (k0 + s) / 2 + tg;
                const uint32_t b1a = gB1u[bi];
                const uint32_t b1b = gB1u[bi + 4];
                const uint32_t b2a = gB2u[bi];
                const uint32_t b2b = gB2u[bi + 4];
#pragma unroll
                for (int mi = 0; mi < 2; mi++) {
                    MMA_BF16(acc[mi][ni], A1f[mi], b1a, b1b);
                    MMA_BF16(acc[mi][ni], A1f[mi], b2a, b2b);
                    MMA_BF16(acc[mi][ni], A2f[mi], b1a, b1b);
                }
            }
        }
        __syncthreads();
    }

    // epilogue: store L fp32
#pragma unroll
    for (int mi = 0; mi < 2; mi++) {
#pragma unroll
        for (int ni = 0; ni < 4; ni++) {
            const int col = wn * 32 + ni * 8 + tg * 2;
            const int r0  = m0 + wm * 32 + mi * 16 + gid;
            if (r0 < Mrows)
                *reinterpret_cast<float2*>(&g_L[(size_t)r0 * Npad + col]) =
                    make_float2(acc[mi][ni][0], acc[mi][ni][1]);
            if (r0 + 8 < Mrows)
                *reinterpret_cast<float2*>(&g_L[(size_t)(r0 + 8) * Npad + col]) =
                    make_float2(acc[mi][ni][2], acc[mi][ni][3]);
        }
    }
}

// ---------------- K2: per-bag softmax-weighted sum of L rows -------------
__global__ __launch_bounds__(256) void out_kernel(
    const float* __restrict__ bias,
    const int*   __restrict__ scope,
    const int*   __restrict__ labels,
    float* __restrict__ out,
    int num_bags)
{
    const int lane = threadIdx.x & 31;
    const int wid  = threadIdx.x >> 5;
    const int bag  = blockIdx.x * 8 + wid;
    if (bag >= num_bags) return;

    const int start = scope[2 * bag];
    const int end   = scope[2 * bag + 1];

    float m = -FLT_MAX;
    for (int i = start + lane; i < end; i += 32)
        m = fmaxf(m, g_L[(size_t)i * Npad + labels[i]]);
    m = wmax(m);

    const int c0 = lane * 2;
    float2 acc = make_float2(0.f, 0.f);
    float s = 0.f;
    for (int i = start; i < end; i++) {
        const float l = g_L[(size_t)i * Npad + labels[i]];   // broadcast
        const float e = __expf(l - m);
        s += e;
        const float2 Lv = *reinterpret_cast<const float2*>(g_L + (size_t)i * Npad + c0);
        acc.x = fmaf(e, Lv.x, acc.x);
        acc.y = fmaf(e, Lv.y, acc.y);
    }
    const float inv = 1.0f / s;
    if (c0 < RR)     out[bag * RR + c0]     = acc.x * inv + bias[c0];
    if (c0 + 1 < RR) out[bag * RR + c0 + 1] = acc.y * inv + bias[c0 + 1];
}

extern "C" void kernel_launch(void* const* d_in, const int* in_sizes, int n_in,
                              void* d_out, int out_size) {
    const float* repre  = (const float*)d_in[0];
    const float* rel    = (const float*)d_in[1];
    const float* bias   = (const float*)d_in[2];
    const int*   scope  = (const int*)d_in[3];
    const int*   labels = (const int*)d_in[4];
    float* out = (float*)d_out;

    const int Mrows    = in_sizes[0] / Dd;    // 200000
    const int num_bags = in_sizes[3] / 2;     // 25000

    convert_kernel<<<(Npad * Kpad + 255) / 256, 256>>>(rel);
    gemm_kernel<<<(Mrows + 127) / 128, 256>>>(repre, Mrows);
    out_kernel<<<(num_bags + 7) / 8, 256>>>(bias, scope, labels, out, num_bags);
}